// round 10
// baseline (speedup 1.0000x reference)
#include <cuda_runtime.h>
#include <cstdint>

#define N_NODES 50000
#define N_EDGES 800000
#define DIM 128
#define SCAN_NB ((N_NODES + 255) / 256)   // 196

// ---------------- scratch (static __device__ arrays; no allocation) ----------
__device__ int   g_deg[N_NODES];
__device__ float g_dinv[N_NODES];
__device__ int   g_rowptr[N_NODES + 1];
__device__ int   g_cursor[N_NODES];
__device__ int   g_bsum[256];
__device__ int   g_csrsrc[N_EDGES];
__device__ float g_csrw[N_EDGES];
__device__ float g_bufA[(size_t)N_NODES * DIM];  // GEMM outputs
__device__ float g_bufB[(size_t)N_NODES * DIM];  // h1
// B = W in mma fragment order, tf32 hi/lo:
// entry e = (ks*16 + ng)*32 + lane ; float2 = (val@k0, val@k0+4),
// k0 = ks*8 + (lane&3), n = ng*8 + (lane>>2)
__device__ float2 g_Bh[3][8192];
__device__ float2 g_Bl[3][8192];

__device__ __forceinline__ uint32_t tf32_hi_bits(float x) {
    uint32_t r;
    asm("cvt.rna.tf32.f32 %0, %1;" : "=r"(r) : "f"(x));
    return r;
}

// D += A(tf32) * B(tf32), m16n8k8
__device__ __forceinline__ void mma_tf32(float* c, const uint32_t* a,
                                         uint32_t b0, uint32_t b1) {
    asm volatile(
        "mma.sync.aligned.m16n8k8.row.col.f32.tf32.tf32.f32 "
        "{%0,%1,%2,%3}, {%4,%5,%6,%7}, {%8,%9}, {%0,%1,%2,%3};"
        : "+f"(c[0]), "+f"(c[1]), "+f"(c[2]), "+f"(c[3])
        : "r"(a[0]), "r"(a[1]), "r"(a[2]), "r"(a[3]), "r"(b0), "r"(b1));
}

// ---------------- weight pre-packing: fragment-ordered tf32 hi/lo -------------
__global__ void pack_w_kernel(const float* __restrict__ W1,
                              const float* __restrict__ W2,
                              const float* __restrict__ Wq) {
    int i = blockIdx.x * blockDim.x + threadIdx.x;
    if (i >= 3 * 8192) return;
    int w = i / 8192, e = i % 8192;
    int ks = e / 512, rem = e % 512;
    int ng = rem / 32, lane = rem % 32;
    int k0 = ks * 8 + (lane & 3);
    int n = ng * 8 + (lane >> 2);
    const float* Ws = (w == 0) ? W1 : (w == 1) ? W2 : Wq;
    float v0 = Ws[k0 * DIM + n];
    float v1 = Ws[(k0 + 4) * DIM + n];
    uint32_t h0 = tf32_hi_bits(v0), h1 = tf32_hi_bits(v1);
    uint32_t l0 = tf32_hi_bits(v0 - __uint_as_float(h0));
    uint32_t l1 = tf32_hi_bits(v1 - __uint_as_float(h1));
    g_Bh[w][e] = make_float2(__uint_as_float(h0), __uint_as_float(h1));
    g_Bl[w][e] = make_float2(__uint_as_float(l0), __uint_as_float(l1));
}

// ---------------- graph preprocessing ----------------------------------------
__global__ void init_deg_kernel() {
    int i = blockIdx.x * blockDim.x + threadIdx.x;
    if (i < N_NODES) g_deg[i] = 1;  // self-loop
}

// edge_index is int32 (JAX x64-disabled downcasts the declared int64)
__global__ void count_kernel(const int* __restrict__ ei) {
    int e = blockIdx.x * blockDim.x + threadIdx.x;
    if (e < N_EDGES) {
        unsigned d = (unsigned)ei[N_EDGES + e];
        if (d < N_NODES) atomicAdd(&g_deg[d], 1);
    }
}

__global__ void scan_phase1_kernel() {
    __shared__ int s[256];
    int t = threadIdx.x;
    int i = blockIdx.x * 256 + t;
    int deg = (i < N_NODES) ? g_deg[i] : 1;
    int val = deg - 1;
    s[t] = val;
    __syncthreads();
#pragma unroll
    for (int off = 1; off < 256; off <<= 1) {
        int v = (t >= off) ? s[t - off] : 0;
        __syncthreads();
        s[t] += v;
        __syncthreads();
    }
    if (i < N_NODES) {
        g_rowptr[i] = s[t] - val;
        g_cursor[i] = 0;
        g_dinv[i] = rsqrtf((float)deg);
    }
    if (t == 255) g_bsum[blockIdx.x] = s[255];
}

__global__ void scan_phase2_kernel() {
    __shared__ int s[256];
    int t = threadIdx.x;
    int v = (t < SCAN_NB) ? g_bsum[t] : 0;
    s[t] = v;
    __syncthreads();
#pragma unroll
    for (int off = 1; off < 256; off <<= 1) {
        int u = (t >= off) ? s[t - off] : 0;
        __syncthreads();
        s[t] += u;
        __syncthreads();
    }
    g_bsum[t] = s[t] - v;
}

__global__ void scan_phase3_kernel() {
    int i = blockIdx.x * 256 + threadIdx.x;
    if (i < N_NODES) g_rowptr[i] += g_bsum[blockIdx.x];
    if (i == 0) g_rowptr[N_NODES] = N_EDGES;
}

__global__ void scatter_kernel(const int* __restrict__ ei) {
    int e = blockIdx.x * blockDim.x + threadIdx.x;
    if (e < N_EDGES) {
        unsigned src = (unsigned)ei[e];
        unsigned dst = (unsigned)ei[N_EDGES + e];
        if (src < N_NODES && dst < N_NODES) {
            int pos = g_rowptr[dst] + atomicAdd(&g_cursor[dst], 1);
            g_csrsrc[pos] = src;
            g_csrw[pos] = g_dinv[src] * g_dinv[dst];
        }
    }
}

// ---------------- GEMM via mma.sync tf32 (3xTF32): C = A @ W (+bias) ----------
// block: 256 threads = 8 warps, tile 64 rows x 128 cols.
// warp grid: 2 (M) x 4 (N); warp tile 32x32 = 2 mtiles x 4 ntiles of m16n8k8.
template <int WSEL, int SRC_BUF, int DST, bool ADD_BIAS>
__global__ void __launch_bounds__(256)
gemm_mma_kernel(const float* __restrict__ A,
                const float* __restrict__ bias,
                float* __restrict__ C, int M) {
    __shared__ float sA[64][132];   // pad 132 -> conflict-free fragment LDS

    const int tid = threadIdx.x;
    const int wid = tid >> 5;
    const int lane = tid & 31;
    const int gid = lane >> 2;      // group id (0..7)
    const int tid4 = lane & 3;      // thread-in-group (0..3)
    const int warpM = (wid & 1) * 32;
    const int warpNg = wid >> 1;    // 0..3 (n-offset = warpNg*32)
    const int row0 = blockIdx.x * 64;

    // load A tile (64x128) -> SMEM
    const float* Abase = SRC_BUF ? g_bufB : A;
    const float4* A4 = (const float4*)Abase;
#pragma unroll
    for (int t = 0; t < 8; t++) {
        int idx = tid + t * 256;          // 0..2047
        int r = idx >> 5, c = idx & 31;
        float4 v = make_float4(0.f, 0.f, 0.f, 0.f);
        if (row0 + r < M) v = A4[(size_t)(row0 + r) * 32 + c];
        *(float4*)&sA[r][c * 4] = v;
    }
    __syncthreads();

    float acc[2][4][4];
#pragma unroll
    for (int mt = 0; mt < 2; mt++)
#pragma unroll
        for (int nt = 0; nt < 4; nt++)
#pragma unroll
            for (int k = 0; k < 4; k++) acc[mt][nt][k] = 0.f;

#pragma unroll 2
    for (int ks = 0; ks < 16; ks++) {
        uint32_t ah[2][4], al[2][4];
#pragma unroll
        for (int mt = 0; mt < 2; mt++) {
            int rb = warpM + mt * 16;
            int col = ks * 8 + tid4;
            float v0 = sA[rb + gid][col];
            float v1 = sA[rb + gid + 8][col];
            float v2 = sA[rb + gid][col + 4];
            float v3 = sA[rb + gid + 8][col + 4];
            ah[mt][0] = tf32_hi_bits(v0);
            ah[mt][1] = tf32_hi_bits(v1);
            ah[mt][2] = tf32_hi_bits(v2);
            ah[mt][3] = tf32_hi_bits(v3);
            al[mt][0] = tf32_hi_bits(v0 - __uint_as_float(ah[mt][0]));
            al[mt][1] = tf32_hi_bits(v1 - __uint_as_float(ah[mt][1]));
            al[mt][2] = tf32_hi_bits(v2 - __uint_as_float(ah[mt][2]));
            al[mt][3] = tf32_hi_bits(v3 - __uint_as_float(ah[mt][3]));
        }
#pragma unroll
        for (int nt = 0; nt < 4; nt++) {
            int ng = warpNg * 4 + nt;
            float2 bh = __ldg(&g_Bh[WSEL][(ks * 16 + ng) * 32 + lane]);
            float2 bl = __ldg(&g_Bl[WSEL][(ks * 16 + ng) * 32 + lane]);
            uint32_t bh0 = __float_as_uint(bh.x), bh1 = __float_as_uint(bh.y);
            uint32_t bl0 = __float_as_uint(bl.x), bl1 = __float_as_uint(bl.y);
#pragma unroll
            for (int mt = 0; mt < 2; mt++) {
                mma_tf32(acc[mt][nt], ah[mt], bh0, bh1);  // Ah*Bh
                mma_tf32(acc[mt][nt], al[mt], bh0, bh1);  // Al*Bh
                mma_tf32(acc[mt][nt], ah[mt], bl0, bl1);  // Ah*Bl
            }
        }
    }

    // epilogue
    float* Cout = DST ? C : g_bufA;
#pragma unroll
    for (int mt = 0; mt < 2; mt++) {
#pragma unroll
        for (int nt = 0; nt < 4; nt++) {
            int col = warpNg * 32 + nt * 8 + tid4 * 2;
            float bx = 0.f, by = 0.f;
            if (ADD_BIAS) {
                float2 bv = ((const float2*)bias)[col >> 1];
                bx = bv.x; by = bv.y;
            }
            int r0 = row0 + warpM + mt * 16 + gid;
            if (r0 < M) {
                float2 o = make_float2(acc[mt][nt][0] + bx, acc[mt][nt][1] + by);
                *(float2*)&Cout[(size_t)r0 * DIM + col] = o;
            }
            if (r0 + 8 < M) {
                float2 o = make_float2(acc[mt][nt][2] + bx, acc[mt][nt][3] + by);
                *(float2*)&Cout[(size_t)(r0 + 8) * DIM + col] = o;
            }
        }
    }
}

// ---------------- aggregation: out[i] = sum_j norm*h[src] + self + bias -------
// 4-deep unrolled CSR walk for gather MLP against L2 latency
template <int DST_BUF, bool RELU>
__global__ void aggregate_kernel(const float* __restrict__ bias,
                                 float* __restrict__ out) {
    int node = blockIdx.x * 8 + threadIdx.y;
    if (node >= N_NODES) return;
    int lane = threadIdx.x;

    const float4* H4 = (const float4*)g_bufA;
    float di = g_dinv[node];
    float w0 = di * di;
    float4 h = H4[(size_t)node * 32 + lane];
    float4 acc = make_float4(h.x * w0, h.y * w0, h.z * w0, h.w * w0);

    int beg = g_rowptr[node];
    int end = g_rowptr[node + 1];
    int j = beg;
    for (; j + 3 < end; j += 4) {
        int s0 = g_csrsrc[j];
        int s1 = g_csrsrc[j + 1];
        int s2 = g_csrsrc[j + 2];
        int s3 = g_csrsrc[j + 3];
        float wa = g_csrw[j];
        float wb = g_csrw[j + 1];
        float wc = g_csrw[j + 2];
        float wd = g_csrw[j + 3];
        float4 v0 = H4[(size_t)s0 * 32 + lane];
        float4 v1 = H4[(size_t)s1 * 32 + lane];
        float4 v2 = H4[(size_t)s2 * 32 + lane];
        float4 v3 = H4[(size_t)s3 * 32 + lane];
        acc.x += v0.x * wa; acc.y += v0.y * wa;
        acc.z += v0.z * wa; acc.w += v0.w * wa;
        acc.x += v1.x * wb; acc.y += v1.y * wb;
        acc.z += v1.z * wb; acc.w += v1.w * wb;
        acc.x += v2.x * wc; acc.y += v2.y * wc;
        acc.z += v2.z * wc; acc.w += v2.w * wc;
        acc.x += v3.x * wd; acc.y += v3.y * wd;
        acc.z += v3.z * wd; acc.w += v3.w * wd;
    }
    for (; j < end; j++) {
        int s = g_csrsrc[j];
        float w = g_csrw[j];
        float4 v = H4[(size_t)s * 32 + lane];
        acc.x += v.x * w; acc.y += v.y * w;
        acc.z += v.z * w; acc.w += v.w * w;
    }

    float4 bv = ((const float4*)bias)[lane];
    acc.x += bv.x; acc.y += bv.y; acc.z += bv.z; acc.w += bv.w;
    if (RELU) {
        acc.x = fmaxf(acc.x, 0.f);
        acc.y = fmaxf(acc.y, 0.f);
        acc.z = fmaxf(acc.z, 0.f);
        acc.w = fmaxf(acc.w, 0.f);
    }
    float4* O = DST_BUF ? (float4*)g_bufB : (float4*)out;
    O[(size_t)node * 32 + lane] = acc;
}

// ---------------- launch ------------------------------------------------------
extern "C" void kernel_launch(void* const* d_in, const int* in_sizes, int n_in,
                              void* d_out, int out_size) {
    const float* x    = (const float*)d_in[0];
    const int*   ei   = (const int*)d_in[1];
    const float* qemb = (const float*)d_in[2];
    const float* W1   = (const float*)d_in[3];
    const float* b1   = (const float*)d_in[4];
    const float* W2   = (const float*)d_in[5];
    const float* b2   = (const float*)d_in[6];
    const float* Wq   = (const float*)d_in[7];
    const float* bq   = (const float*)d_in[8];

    float* out = (float*)d_out;
    float* out_ques = out;                          // [20000,128]
    float* out_h2   = out + (size_t)20000 * DIM;    // [50000,128]

    // side streams/events for DAG parallelism (created once; creation happens
    // host-side and is not a captured graph node)
    static cudaStream_t sPre = nullptr, sQ = nullptr;
    static cudaEvent_t evRoot = nullptr, evPack = nullptr, evPre = nullptr,
                       evQ = nullptr;
    if (sPre == nullptr) {
        cudaStreamCreateWithFlags(&sPre, cudaStreamNonBlocking);
        cudaStreamCreateWithFlags(&sQ, cudaStreamNonBlocking);
        cudaEventCreateWithFlags(&evRoot, cudaEventDisableTiming);
        cudaEventCreateWithFlags(&evPack, cudaEventDisableTiming);
        cudaEventCreateWithFlags(&evPre, cudaEventDisableTiming);
        cudaEventCreateWithFlags(&evQ, cudaEventDisableTiming);
    }

    // fork: CSR build on sPre (independent of weights/gemm1)
    cudaEventRecord(evRoot, 0);
    cudaStreamWaitEvent(sPre, evRoot, 0);
    init_deg_kernel<<<(N_NODES + 255) / 256, 256, 0, sPre>>>();
    count_kernel<<<(N_EDGES + 255) / 256, 256, 0, sPre>>>(ei);
    scan_phase1_kernel<<<SCAN_NB, 256, 0, sPre>>>();
    scan_phase2_kernel<<<1, 256, 0, sPre>>>();
    scan_phase3_kernel<<<SCAN_NB, 256, 0, sPre>>>();
    scatter_kernel<<<(N_EDGES + 255) / 256, 256, 0, sPre>>>(ei);
    cudaEventRecord(evPre, sPre);

    // main stream: pack weights, then layer-1 GEMM
    pack_w_kernel<<<(3 * 8192 + 255) / 256, 256>>>(W1, W2, Wq);
    cudaEventRecord(evPack, 0);

    // question GEMM on sQ (needs only pack; joins at the end)
    cudaStreamWaitEvent(sQ, evPack, 0);
    gemm_mma_kernel<2, 0, 1, true><<<(20000 + 63) / 64, 256, 0, sQ>>>(
        qemb, bq, out_ques, 20000);
    cudaEventRecord(evQ, sQ);

    // layer 1: g_bufA = x @ W1 ; g_bufB = relu(agg(g_bufA) + b1)
    gemm_mma_kernel<0, 0, 0, false><<<(N_NODES + 63) / 64, 256>>>(x, nullptr, nullptr, N_NODES);
    cudaStreamWaitEvent(0, evPre, 0);
    aggregate_kernel<1, true><<<(N_NODES + 7) / 8, dim3(32, 8)>>>(b1, nullptr);
    // layer 2: g_bufA = g_bufB @ W2 ; out_h2 = agg(g_bufA) + b2
    gemm_mma_kernel<1, 1, 0, false><<<(N_NODES + 63) / 64, 256>>>(nullptr, nullptr, nullptr, N_NODES);
    aggregate_kernel<0, false><<<(N_NODES + 7) / 8, dim3(32, 8)>>>(b2, out_h2);
    // join question path
    cudaStreamWaitEvent(0, evQ, 0);
}

// round 11
// speedup vs baseline: 1.2924x; 1.2924x over previous
#include <cuda_runtime.h>
#include <cstdint>

#define N_NODES 50000
#define N_EDGES 800000
#define DIM 128
#define SCAN_NB ((N_NODES + 255) / 256)   // 196

// ---------------- scratch (static __device__ arrays; no allocation) ----------
__device__ int   g_deg[N_NODES];
__device__ float g_dinv[N_NODES];
__device__ int   g_rowptr[N_NODES + 1];
__device__ int   g_cursor[N_NODES];
__device__ int   g_bsum[256];
__device__ int   g_csrsrc[N_EDGES];
__device__ float g_csrw[N_EDGES];
__device__ float g_bufA[(size_t)N_NODES * DIM];  // GEMM outputs
__device__ float g_bufB[(size_t)N_NODES * DIM];  // h1
// B = W in mma fragment order, tf32 hi/lo:
// entry e = (ks*16 + ng)*32 + lane ; float2 = (val@k0, val@k0+4),
// k0 = ks*8 + (lane&3), n = ng*8 + (lane>>2)
__device__ float2 g_Bh[3][8192];
__device__ float2 g_Bl[3][8192];

__device__ __forceinline__ uint32_t tf32_hi_bits(float x) {
    uint32_t r;
    asm("cvt.rna.tf32.f32 %0, %1;" : "=r"(r) : "f"(x));
    return r;
}

// D += A(tf32) * B(tf32), m16n8k8
__device__ __forceinline__ void mma_tf32(float* c, const uint32_t* a,
                                         uint32_t b0, uint32_t b1) {
    asm volatile(
        "mma.sync.aligned.m16n8k8.row.col.f32.tf32.tf32.f32 "
        "{%0,%1,%2,%3}, {%4,%5,%6,%7}, {%8,%9}, {%0,%1,%2,%3};"
        : "+f"(c[0]), "+f"(c[1]), "+f"(c[2]), "+f"(c[3])
        : "r"(a[0]), "r"(a[1]), "r"(a[2]), "r"(a[3]), "r"(b0), "r"(b1));
}

// ---------------- weight pre-packing: fragment-ordered tf32 hi/lo -------------
__global__ void pack_w_kernel(const float* __restrict__ W1,
                              const float* __restrict__ W2,
                              const float* __restrict__ Wq) {
    int i = blockIdx.x * blockDim.x + threadIdx.x;
    if (i >= 3 * 8192) return;
    int w = i / 8192, e = i % 8192;
    int ks = e / 512, rem = e % 512;
    int ng = rem / 32, lane = rem % 32;
    int k0 = ks * 8 + (lane & 3);
    int n = ng * 8 + (lane >> 2);
    const float* Ws = (w == 0) ? W1 : (w == 1) ? W2 : Wq;
    float v0 = Ws[k0 * DIM + n];
    float v1 = Ws[(k0 + 4) * DIM + n];
    uint32_t h0 = tf32_hi_bits(v0), h1 = tf32_hi_bits(v1);
    uint32_t l0 = tf32_hi_bits(v0 - __uint_as_float(h0));
    uint32_t l1 = tf32_hi_bits(v1 - __uint_as_float(h1));
    g_Bh[w][e] = make_float2(__uint_as_float(h0), __uint_as_float(h1));
    g_Bl[w][e] = make_float2(__uint_as_float(l0), __uint_as_float(l1));
}

// ---------------- graph preprocessing ----------------------------------------
__global__ void init_deg_kernel() {
    int i = blockIdx.x * blockDim.x + threadIdx.x;
    if (i < N_NODES) g_deg[i] = 1;  // self-loop
}

// edge_index is int32 (JAX x64-disabled downcasts the declared int64)
__global__ void count_kernel(const int* __restrict__ ei) {
    int e = blockIdx.x * blockDim.x + threadIdx.x;
    if (e < N_EDGES) {
        unsigned d = (unsigned)ei[N_EDGES + e];
        if (d < N_NODES) atomicAdd(&g_deg[d], 1);
    }
}

__global__ void scan_phase1_kernel() {
    __shared__ int s[256];
    int t = threadIdx.x;
    int i = blockIdx.x * 256 + t;
    int deg = (i < N_NODES) ? g_deg[i] : 1;
    int val = deg - 1;
    s[t] = val;
    __syncthreads();
#pragma unroll
    for (int off = 1; off < 256; off <<= 1) {
        int v = (t >= off) ? s[t - off] : 0;
        __syncthreads();
        s[t] += v;
        __syncthreads();
    }
    if (i < N_NODES) {
        g_rowptr[i] = s[t] - val;
        g_cursor[i] = 0;
        g_dinv[i] = rsqrtf((float)deg);
    }
    if (t == 255) g_bsum[blockIdx.x] = s[255];
}

__global__ void scan_phase2_kernel() {
    __shared__ int s[256];
    int t = threadIdx.x;
    int v = (t < SCAN_NB) ? g_bsum[t] : 0;
    s[t] = v;
    __syncthreads();
#pragma unroll
    for (int off = 1; off < 256; off <<= 1) {
        int u = (t >= off) ? s[t - off] : 0;
        __syncthreads();
        s[t] += u;
        __syncthreads();
    }
    g_bsum[t] = s[t] - v;
}

__global__ void scan_phase3_kernel() {
    int i = blockIdx.x * 256 + threadIdx.x;
    if (i < N_NODES) g_rowptr[i] += g_bsum[blockIdx.x];
    if (i == 0) g_rowptr[N_NODES] = N_EDGES;
}

__global__ void scatter_kernel(const int* __restrict__ ei) {
    int e = blockIdx.x * blockDim.x + threadIdx.x;
    if (e < N_EDGES) {
        unsigned src = (unsigned)ei[e];
        unsigned dst = (unsigned)ei[N_EDGES + e];
        if (src < N_NODES && dst < N_NODES) {
            int pos = g_rowptr[dst] + atomicAdd(&g_cursor[dst], 1);
            g_csrsrc[pos] = src;
            g_csrw[pos] = g_dinv[src] * g_dinv[dst];
        }
    }
}

// ---------------- GEMM via mma.sync tf32 (3xTF32): C = A @ W (+bias) ----------
// block: 256 threads = 8 warps, tile 64 rows x 128 cols.
// warp grid: 2 (M) x 4 (N); warp tile 32x32 = 2 mtiles x 4 ntiles of m16n8k8.
template <int WSEL, int SRC_BUF, int DST, bool ADD_BIAS>
__global__ void __launch_bounds__(256)
gemm_mma_kernel(const float* __restrict__ A,
                const float* __restrict__ bias,
                float* __restrict__ C, int M) {
    __shared__ float sA[64][132];   // pad 132 -> conflict-free fragment LDS

    const int tid = threadIdx.x;
    const int wid = tid >> 5;
    const int lane = tid & 31;
    const int gid = lane >> 2;      // group id (0..7)
    const int tid4 = lane & 3;      // thread-in-group (0..3)
    const int warpM = (wid & 1) * 32;
    const int warpNg = wid >> 1;    // 0..3 (n-offset = warpNg*32)
    const int row0 = blockIdx.x * 64;

    // load A tile (64x128) -> SMEM
    const float* Abase = SRC_BUF ? g_bufB : A;
    const float4* A4 = (const float4*)Abase;
#pragma unroll
    for (int t = 0; t < 8; t++) {
        int idx = tid + t * 256;          // 0..2047
        int r = idx >> 5, c = idx & 31;
        float4 v = make_float4(0.f, 0.f, 0.f, 0.f);
        if (row0 + r < M) v = A4[(size_t)(row0 + r) * 32 + c];
        *(float4*)&sA[r][c * 4] = v;
    }
    __syncthreads();

    float acc[2][4][4];
#pragma unroll
    for (int mt = 0; mt < 2; mt++)
#pragma unroll
        for (int nt = 0; nt < 4; nt++)
#pragma unroll
            for (int k = 0; k < 4; k++) acc[mt][nt][k] = 0.f;

#pragma unroll 2
    for (int ks = 0; ks < 16; ks++) {
        uint32_t ah[2][4], al[2][4];
#pragma unroll
        for (int mt = 0; mt < 2; mt++) {
            int rb = warpM + mt * 16;
            int col = ks * 8 + tid4;
            float v0 = sA[rb + gid][col];
            float v1 = sA[rb + gid + 8][col];
            float v2 = sA[rb + gid][col + 4];
            float v3 = sA[rb + gid + 8][col + 4];
            ah[mt][0] = tf32_hi_bits(v0);
            ah[mt][1] = tf32_hi_bits(v1);
            ah[mt][2] = tf32_hi_bits(v2);
            ah[mt][3] = tf32_hi_bits(v3);
            al[mt][0] = tf32_hi_bits(v0 - __uint_as_float(ah[mt][0]));
            al[mt][1] = tf32_hi_bits(v1 - __uint_as_float(ah[mt][1]));
            al[mt][2] = tf32_hi_bits(v2 - __uint_as_float(ah[mt][2]));
            al[mt][3] = tf32_hi_bits(v3 - __uint_as_float(ah[mt][3]));
        }
#pragma unroll
        for (int nt = 0; nt < 4; nt++) {
            int ng = warpNg * 4 + nt;
            float2 bh = __ldg(&g_Bh[WSEL][(ks * 16 + ng) * 32 + lane]);
            float2 bl = __ldg(&g_Bl[WSEL][(ks * 16 + ng) * 32 + lane]);
            uint32_t bh0 = __float_as_uint(bh.x), bh1 = __float_as_uint(bh.y);
            uint32_t bl0 = __float_as_uint(bl.x), bl1 = __float_as_uint(bl.y);
#pragma unroll
            for (int mt = 0; mt < 2; mt++) {
                mma_tf32(acc[mt][nt], ah[mt], bh0, bh1);  // Ah*Bh
                mma_tf32(acc[mt][nt], al[mt], bh0, bh1);  // Al*Bh
                mma_tf32(acc[mt][nt], ah[mt], bl0, bl1);  // Ah*Bl
            }
        }
    }

    // epilogue
    float* Cout = DST ? C : g_bufA;
#pragma unroll
    for (int mt = 0; mt < 2; mt++) {
#pragma unroll
        for (int nt = 0; nt < 4; nt++) {
            int col = warpNg * 32 + nt * 8 + tid4 * 2;
            float bx = 0.f, by = 0.f;
            if (ADD_BIAS) {
                float2 bv = ((const float2*)bias)[col >> 1];
                bx = bv.x; by = bv.y;
            }
            int r0 = row0 + warpM + mt * 16 + gid;
            if (r0 < M) {
                float2 o = make_float2(acc[mt][nt][0] + bx, acc[mt][nt][1] + by);
                *(float2*)&Cout[(size_t)r0 * DIM + col] = o;
            }
            if (r0 + 8 < M) {
                float2 o = make_float2(acc[mt][nt][2] + bx, acc[mt][nt][3] + by);
                *(float2*)&Cout[(size_t)(r0 + 8) * DIM + col] = o;
            }
        }
    }
}

// ---------------- aggregation: out[i] = sum_j norm*h[src] + self + bias -------
// 4-deep unrolled CSR walk for gather MLP against L2 latency
template <int DST_BUF, bool RELU>
__global__ void aggregate_kernel(const float* __restrict__ bias,
                                 float* __restrict__ out) {
    int node = blockIdx.x * 8 + threadIdx.y;
    if (node >= N_NODES) return;
    int lane = threadIdx.x;

    const float4* H4 = (const float4*)g_bufA;
    float di = g_dinv[node];
    float w0 = di * di;
    float4 h = H4[(size_t)node * 32 + lane];
    float4 acc = make_float4(h.x * w0, h.y * w0, h.z * w0, h.w * w0);

    int beg = g_rowptr[node];
    int end = g_rowptr[node + 1];
    int j = beg;
    for (; j + 3 < end; j += 4) {
        int s0 = g_csrsrc[j];
        int s1 = g_csrsrc[j + 1];
        int s2 = g_csrsrc[j + 2];
        int s3 = g_csrsrc[j + 3];
        float wa = g_csrw[j];
        float wb = g_csrw[j + 1];
        float wc = g_csrw[j + 2];
        float wd = g_csrw[j + 3];
        float4 v0 = H4[(size_t)s0 * 32 + lane];
        float4 v1 = H4[(size_t)s1 * 32 + lane];
        float4 v2 = H4[(size_t)s2 * 32 + lane];
        float4 v3 = H4[(size_t)s3 * 32 + lane];
        acc.x += v0.x * wa; acc.y += v0.y * wa;
        acc.z += v0.z * wa; acc.w += v0.w * wa;
        acc.x += v1.x * wb; acc.y += v1.y * wb;
        acc.z += v1.z * wb; acc.w += v1.w * wb;
        acc.x += v2.x * wc; acc.y += v2.y * wc;
        acc.z += v2.z * wc; acc.w += v2.w * wc;
        acc.x += v3.x * wd; acc.y += v3.y * wd;
        acc.z += v3.z * wd; acc.w += v3.w * wd;
    }
    for (; j < end; j++) {
        int s = g_csrsrc[j];
        float w = g_csrw[j];
        float4 v = H4[(size_t)s * 32 + lane];
        acc.x += v.x * w; acc.y += v.y * w;
        acc.z += v.z * w; acc.w += v.w * w;
    }

    float4 bv = ((const float4*)bias)[lane];
    acc.x += bv.x; acc.y += bv.y; acc.z += bv.z; acc.w += bv.w;
    if (RELU) {
        acc.x = fmaxf(acc.x, 0.f);
        acc.y = fmaxf(acc.y, 0.f);
        acc.z = fmaxf(acc.z, 0.f);
        acc.w = fmaxf(acc.w, 0.f);
    }
    float4* O = DST_BUF ? (float4*)g_bufB : (float4*)out;
    O[(size_t)node * 32 + lane] = acc;
}

// ---------------- launch (serial chain — streams regressed in R10) ------------
extern "C" void kernel_launch(void* const* d_in, const int* in_sizes, int n_in,
                              void* d_out, int out_size) {
    const float* x    = (const float*)d_in[0];
    const int*   ei   = (const int*)d_in[1];
    const float* qemb = (const float*)d_in[2];
    const float* W1   = (const float*)d_in[3];
    const float* b1   = (const float*)d_in[4];
    const float* W2   = (const float*)d_in[5];
    const float* b2   = (const float*)d_in[6];
    const float* Wq   = (const float*)d_in[7];
    const float* bq   = (const float*)d_in[8];

    float* out = (float*)d_out;
    float* out_ques = out;                          // [20000,128]
    float* out_h2   = out + (size_t)20000 * DIM;    // [50000,128]

    // weight packing + graph preprocessing
    pack_w_kernel<<<(3 * 8192 + 255) / 256, 256>>>(W1, W2, Wq);
    init_deg_kernel<<<(N_NODES + 255) / 256, 256>>>();
    count_kernel<<<(N_EDGES + 255) / 256, 256>>>(ei);
    scan_phase1_kernel<<<SCAN_NB, 256>>>();
    scan_phase2_kernel<<<1, 256>>>();
    scan_phase3_kernel<<<SCAN_NB, 256>>>();
    scatter_kernel<<<(N_EDGES + 255) / 256, 256>>>(ei);

    // layer 1: g_bufA = x @ W1 ; g_bufB = relu(agg(g_bufA) + b1)
    gemm_mma_kernel<0, 0, 0, false><<<(N_NODES + 63) / 64, 256>>>(x, nullptr, nullptr, N_NODES);
    aggregate_kernel<1, true><<<(N_NODES + 7) / 8, dim3(32, 8)>>>(b1, nullptr);
    // layer 2: g_bufA = g_bufB @ W2 ; out_h2 = agg(g_bufA) + b2
    gemm_mma_kernel<1, 1, 0, false><<<(N_NODES + 63) / 64, 256>>>(nullptr, nullptr, nullptr, N_NODES);
    aggregate_kernel<0, false><<<(N_NODES + 7) / 8, dim3(32, 8)>>>(b2, out_h2);
    // question path: ques = q_emb @ Wq + bq
    gemm_mma_kernel<2, 0, 1, true><<<(20000 + 63) / 64, 256>>>(qemb, bq, out_ques, 20000);
}